// round 13
// baseline (speedup 1.0000x reference)
#include <cuda_runtime.h>
#include <cuda_fp16.h>
#include <cstdint>

// out[m][d] = sum_k ecg[m*128+k] * W[d*128+k] + b[d],  M=196608, K=128, N=64.
// 2-term fp16 HMMA: D = A16*Whi + A16*Wlo (fp32 accum).
// This revision combines (for the first time): 16 warps/SM (256thr, <=128 regs),
// cp.async 3-stage A pipeline (barrier-free: lanes consume self-produced bytes),
// and the smem-staged coalesced epilogue.

#define THREADS 256
#define BM 256            // 8 warps x 32 rows
#define WPAD 136          // fp16 per padded W row
#define AROWB 80          // A-chunk row stride in bytes (64B data + 16B pad)
#define ASTAGEB (256 * AROWB)   // 20480 B per stage
#define NSTAGE 3
#define A_OFF 34816       // W region: 2 * 64 * WPAD * 2 = 34816 B
#define SMEM_TOTAL (A_OFF + NSTAGE * ASTAGEB)   // 96256 B
#define STG_STRIDE 68     // epilogue staging row stride (floats); 8w x 16 x 68 x 4 = 34816

__device__ __forceinline__ uint32_t s2u(const void* p) {
    uint32_t a;
    asm("{ .reg .u64 t; cvta.to.shared.u64 t, %1; cvt.u32.u64 %0, t; }" : "=r"(a) : "l"(p));
    return a;
}

__device__ __forceinline__ uint32_t f16x2(float x, float y) {
    uint32_t r;
    asm("cvt.rn.f16x2.f32 %0, %1, %2;" : "=r"(r) : "f"(y), "f"(x));
    return r;
}

__device__ __forceinline__ void split2h(float x, float y, uint32_t& hi, uint32_t& lo) {
    hi = f16x2(x, y);
    __half2 h = *reinterpret_cast<__half2*>(&hi);
    float2 hf = __half22float2(h);
    lo = f16x2(x - hf.x, y - hf.y);
}

__device__ __forceinline__ void ldsm4(uint32_t* r, uint32_t addr) {
    asm volatile("ldmatrix.sync.aligned.m8n8.x4.shared.b16 {%0,%1,%2,%3}, [%4];"
                 : "=r"(r[0]), "=r"(r[1]), "=r"(r[2]), "=r"(r[3]) : "r"(addr));
}

__device__ __forceinline__ void mma16816h(float* c,
                                          uint32_t a0, uint32_t a1, uint32_t a2, uint32_t a3,
                                          uint32_t b0, uint32_t b1) {
    asm volatile(
        "mma.sync.aligned.m16n8k16.row.col.f32.f16.f16.f32 "
        "{%0,%1,%2,%3}, {%4,%5,%6,%7}, {%8,%9}, {%0,%1,%2,%3};"
        : "+f"(c[0]), "+f"(c[1]), "+f"(c[2]), "+f"(c[3])
        : "r"(a0), "r"(a1), "r"(a2), "r"(a3), "r"(b0), "r"(b1));
}

__device__ __forceinline__ void cpa16(uint32_t dst, const float* src) {
    asm volatile("cp.async.cg.shared.global [%0], [%1], 16;" :: "r"(dst), "l"(src));
}
__device__ __forceinline__ void cpa_commit() {
    asm volatile("cp.async.commit_group;" ::: "memory");
}
template <int N>
__device__ __forceinline__ void cpa_wait() {
    asm volatile("cp.async.wait_group %0;" :: "n"(N) : "memory");
}

__global__ __launch_bounds__(THREADS, 2)
void ecg_tok_mma(const float* __restrict__ ecg,
                 const float* __restrict__ W,
                 const float* __restrict__ bias,
                 float* __restrict__ out,
                 long long xelems, int fillCount) {
    extern __shared__ __align__(16) char smem[];
    uint32_t* Whi32 = reinterpret_cast<uint32_t*>(smem);
    uint32_t* Wlo32 = Whi32 + 64 * WPAD / 2;
    const uint32_t sb = s2u(smem);

    const int tid  = threadIdx.x;
    const int warp = tid >> 5;
    const int lane = tid & 31;
    const long long m0 = (long long)blockIdx.x * BM;

    // ---- folded fill: beat_intervals tail ----
    {
        int fi = blockIdx.x * THREADS + tid;
        if (fi < fillCount) out[xelems + fi] = 128.0f;
    }

    // ---- prologue: load + split W (fp16 hi/lo) with per-16-chunk column perm ----
    // global pair g of a chunk -> slice pair (g>>1) + (g&1)*4 (same perm on A).
    #pragma unroll
    for (int it = 0; it < 8; it++) {
        int idx   = tid + it * THREADS;     // 0..2047
        int n     = idx >> 5;
        int r     = idx & 31;
        int chunk = r >> 2;
        int q     = r & 3;
        float4 v = *reinterpret_cast<const float4*>(W + n * 128 + chunk * 16 + q * 4);
        uint32_t h0, l0, h1, l1;
        split2h(v.x, v.y, h0, l0);
        split2h(v.z, v.w, h1, l1);
        int u = n * (WPAD / 2) + chunk * 8 + q;
        Whi32[u]     = h0;
        Whi32[u + 4] = h1;
        Wlo32[u]     = l0;
        Wlo32[u + 4] = l1;
    }
    __syncthreads();

    // ldmatrix lane addressing
    const int lm_row  = ((lane >> 4) << 3) + (lane & 7);
    const int lm_kofs = ((lane >> 3) & 1) << 4;
    const uint32_t lm_term  = (uint32_t)(lm_row * (WPAD * 2) + lm_kofs);
    const uint32_t whi_base = sb + lm_term;
    const uint32_t wlo_base = sb + 64 * WPAD * 2 + lm_term;

    // ---- A cp.async geometry (warp owns rows warp*32 .. warp*32+31) ----
    // copy: lane handles rows (lane>>2)+8j (j=0..3), seg lane&3  -> 4 cp.async.
    // consume: lane reads rows (lane>>2)+8j, seg lane&3 -> self-produced bytes,
    // so cp.async.wait_group per-thread suffices; no barriers in mainloop.
    const uint32_t a_warp = sb + A_OFF + (uint32_t)(warp * 32 * AROWB);
    const float* g_warp   = ecg + (m0 + warp * 32) * 128;

    const int cp_row0 = lane >> 2;     // + 8j
    const int cp_seg  = lane & 3;

    auto issue_chunk = [&](int s, int st) {
        const uint32_t dst0 = a_warp +
            (uint32_t)(st * ASTAGEB + cp_row0 * AROWB + cp_seg * 16);
        const float* src0 = g_warp + cp_row0 * 128 + s * 16 + cp_seg * 4;
        #pragma unroll
        for (int j = 0; j < 4; j++)
            cpa16(dst0 + (uint32_t)(j * 8 * AROWB), src0 + j * 8 * 128);
        cpa_commit();
    };

    // fragment LDS base: row (lane>>2), seg (lane&3)
    const uint32_t fbase_off = (uint32_t)(A_OFF + warp * 32 * AROWB
                                          + (lane >> 2) * AROWB + (lane & 3) * 16);

    float acc[2][8][4];
    #pragma unroll
    for (int f = 0; f < 2; f++)
        #pragma unroll
        for (int nt = 0; nt < 8; nt++)
            #pragma unroll
            for (int j = 0; j < 4; j++) acc[f][nt][j] = 0.0f;

    issue_chunk(0, 0);
    issue_chunk(1, 1);

    #pragma unroll
    for (int s = 0; s < 8; s++) {
        const int st = s % NSTAGE;

        if (s + 2 < 8) issue_chunk(s + 2, (s + 2) % NSTAGE);

        if (s < 6)       cpa_wait<2>();
        else if (s == 6) cpa_wait<1>();
        else             cpa_wait<0>();

        // load + convert A fragments (4 LDS.128, conflict-free, own-lane data)
        uint32_t ah[8];
        #pragma unroll
        for (int j = 0; j < 4; j++) {
            float4 v = *reinterpret_cast<const float4*>(
                smem + fbase_off + st * ASTAGEB + j * 8 * AROWB);
            ah[2 * j]     = f16x2(v.x, v.y);
            ah[2 * j + 1] = f16x2(v.z, v.w);
        }

        #pragma unroll
        for (int ntp = 0; ntp < 4; ntp++) {
            const uint32_t off = (uint32_t)(ntp * 16 * WPAD * 2 + s * 32);
            uint32_t bh[4], bl[4];
            ldsm4(bh, whi_base + off);
            ldsm4(bl, wlo_base + off);

            // frag f: a0=ah[4f], a1=ah[4f+2], a2=ah[4f+1], a3=ah[4f+3]
            #pragma unroll
            for (int f = 0; f < 2; f++) {
                mma16816h(acc[f][2 * ntp],     ah[4*f], ah[4*f+2], ah[4*f+1], ah[4*f+3],
                          bh[0], bh[1]);
                mma16816h(acc[f][2 * ntp + 1], ah[4*f], ah[4*f+2], ah[4*f+1], ah[4*f+3],
                          bh[2], bh[3]);
            }
            #pragma unroll
            for (int f = 0; f < 2; f++) {
                mma16816h(acc[f][2 * ntp],     ah[4*f], ah[4*f+2], ah[4*f+1], ah[4*f+3],
                          bl[0], bl[1]);
                mma16816h(acc[f][2 * ntp + 1], ah[4*f], ah[4*f+2], ah[4*f+1], ah[4*f+3],
                          bl[2], bl[3]);
            }
        }
    }

    // ---- epilogue: stage per-warp in smem (reuses W region), coalesced STG ----
    __syncthreads();   // all warps done reading W smem

    float* stage = reinterpret_cast<float*>(smem) + warp * (16 * STG_STRIDE);
    const float4 bv4 = reinterpret_cast<const float4*>(bias)[lane & 15];
    const int r0 = lane >> 2;
    const int c0 = 2 * (lane & 3);
    const int rr = lane >> 4;
    const int cc = lane & 15;

    #pragma unroll
    for (int f = 0; f < 2; f++) {
        __syncwarp();
        #pragma unroll
        for (int nt = 0; nt < 8; nt++) {
            *reinterpret_cast<float2*>(&stage[STG_STRIDE * r0 + 8 * nt + c0]) =
                make_float2(acc[f][nt][0], acc[f][nt][1]);
            *reinterpret_cast<float2*>(&stage[STG_STRIDE * (r0 + 8) + 8 * nt + c0]) =
                make_float2(acc[f][nt][2], acc[f][nt][3]);
        }
        __syncwarp();

        const long long rowbase = m0 + warp * 32 + f * 16;
        #pragma unroll
        for (int i = 0; i < 8; i++) {
            int r = 2 * i + rr;
            float4 v = *reinterpret_cast<float4*>(&stage[STG_STRIDE * r + 4 * cc]);
            v.x += bv4.x; v.y += bv4.y; v.z += bv4.z; v.w += bv4.w;
            *reinterpret_cast<float4*>(out + (rowbase + r) * 64 + 4 * cc) = v;
        }
    }
}

extern "C" void kernel_launch(void* const* d_in, const int* in_sizes, int n_in,
                              void* d_out, int out_size) {
    const float* ecg = (const float*)d_in[0];
    const float* W   = (const float*)d_in[1];
    const float* b   = (const float*)d_in[2];
    float* out = (float*)d_out;

    const int M = in_sizes[0] / 128;
    const long long xelems = (long long)M * 64;
    const int fillCount = out_size - (int)xelems;

    cudaFuncSetAttribute(ecg_tok_mma, cudaFuncAttributeMaxDynamicSharedMemorySize,
                         SMEM_TOTAL);
    ecg_tok_mma<<<M / BM, THREADS, SMEM_TOTAL>>>(ecg, W, b, out, xelems, fillCount);
}

// round 14
// speedup vs baseline: 1.1043x; 1.1043x over previous
#include <cuda_runtime.h>
#include <cuda_fp16.h>
#include <cstdint>

// out[m][d] = sum_k ecg[m*128+k] * W[d*128+k] + b[d],  M=196608, K=128, N=64.
// 2-term fp16 HMMA: D = A16*Whi + A16*Wlo (fp32 accum), rel_err ~2e-4.
// R14 = R10 config (BM=128, 4 CTAs/SM, direct permuted LDG for A)
//     + R11 epilogue (smem-staged coalesced STG.128, reusing W region).

#define THREADS 128
#define BM 128
#define WPAD 136         // fp16 per padded W row (272 B -> conflict-free ldmatrix)
#define W_BYTES (2 * 64 * WPAD * 2)   // 34816 B (hi + lo tiles)
#define STG_STRIDE 72    // epilogue staging row stride in floats (conflict-free)

__device__ __forceinline__ uint32_t s2u(const void* p) {
    uint32_t a;
    asm("{ .reg .u64 t; cvta.to.shared.u64 t, %1; cvt.u32.u64 %0, t; }" : "=r"(a) : "l"(p));
    return a;
}

__device__ __forceinline__ uint32_t f16x2(float x, float y) {
    uint32_t r;
    asm("cvt.rn.f16x2.f32 %0, %1, %2;" : "=r"(r) : "f"(y), "f"(x));
    return r;
}

__device__ __forceinline__ void split2h(float x, float y, uint32_t& hi, uint32_t& lo) {
    hi = f16x2(x, y);
    __half2 h = *reinterpret_cast<__half2*>(&hi);
    float2 hf = __half22float2(h);
    lo = f16x2(x - hf.x, y - hf.y);
}

__device__ __forceinline__ void ldsm4(uint32_t* r, uint32_t addr) {
    asm volatile("ldmatrix.sync.aligned.m8n8.x4.shared.b16 {%0,%1,%2,%3}, [%4];"
                 : "=r"(r[0]), "=r"(r[1]), "=r"(r[2]), "=r"(r[3]) : "r"(addr));
}

__device__ __forceinline__ void mma16816h(float* c,
                                          uint32_t a0, uint32_t a1, uint32_t a2, uint32_t a3,
                                          uint32_t b0, uint32_t b1) {
    asm volatile(
        "mma.sync.aligned.m16n8k16.row.col.f32.f16.f16.f32 "
        "{%0,%1,%2,%3}, {%4,%5,%6,%7}, {%8,%9}, {%0,%1,%2,%3};"
        : "+f"(c[0]), "+f"(c[1]), "+f"(c[2]), "+f"(c[3])
        : "r"(a0), "r"(a1), "r"(a2), "r"(a3), "r"(b0), "r"(b1));
}

__global__ __launch_bounds__(THREADS, 4)
void ecg_tok_mma(const float* __restrict__ ecg,
                 const float* __restrict__ W,
                 const float* __restrict__ bias,
                 float* __restrict__ out,
                 long long xelems, int fillCount) {
    // W hi/lo tiles; after the mainloop the same region is reused as the
    // epilogue staging buffer (one __syncthreads separates the two uses).
    __shared__ __align__(16) char smem_raw[W_BYTES];
    uint32_t* Whi32 = reinterpret_cast<uint32_t*>(smem_raw);
    uint32_t* Wlo32 = Whi32 + 64 * WPAD / 2;

    const int tid  = threadIdx.x;
    const int warp = tid >> 5;
    const int lane = tid & 31;
    const long long m0 = (long long)blockIdx.x * BM;

    // ---- folded fill: beat_intervals tail ----
    {
        int fi = blockIdx.x * THREADS + tid;
        if (fi < fillCount) out[xelems + fi] = 128.0f;
    }

    // ---- prologue: load + split W (fp16 hi/lo) with per-16-chunk column perm ----
    // global pair g of a chunk -> slice pair (g>>1) + (g&1)*4 (same perm on A).
    #pragma unroll
    for (int it = 0; it < 16; it++) {
        int idx   = tid + it * THREADS;     // 0..2047
        int n     = idx >> 5;
        int r     = idx & 31;
        int chunk = r >> 2;
        int q     = r & 3;
        float4 v = *reinterpret_cast<const float4*>(W + n * 128 + chunk * 16 + q * 4);
        uint32_t h0, l0, h1, l1;
        split2h(v.x, v.y, h0, l0);
        split2h(v.z, v.w, h1, l1);
        int u = n * (WPAD / 2) + chunk * 8 + q;
        Whi32[u]     = h0;
        Whi32[u + 4] = h1;
        Wlo32[u]     = l0;
        Wlo32[u + 4] = l1;
    }
    __syncthreads();

    // ldmatrix lane addressing
    const int lm_row  = ((lane >> 4) << 3) + (lane & 7);
    const int lm_kofs = ((lane >> 3) & 1) << 4;   // bytes
    const uint32_t lm_term  = (uint32_t)(lm_row * (WPAD * 2) + lm_kofs);
    const uint32_t whi_base = s2u(Whi32) + lm_term;
    const uint32_t wlo_base = s2u(Wlo32) + lm_term;

    // A geometry: warp rows = warp*32 + {0..31}; lane float4 at col 4*(lane&3)
    const int arow = warp * 32 + (lane >> 2);
    const float* abase = ecg + (m0 + arow) * 128 + 4 * (lane & 3);

    float acc[2][8][4];
    #pragma unroll
    for (int f = 0; f < 2; f++)
        #pragma unroll
        for (int nt = 0; nt < 8; nt++)
            #pragma unroll
            for (int j = 0; j < 4; j++) acc[f][nt][j] = 0.0f;

    // A prefetch (1-deep)
    float4 cur[4];
    #pragma unroll
    for (int j = 0; j < 4; j++)
        cur[j] = *reinterpret_cast<const float4*>(abase + j * 8 * 128);

    #pragma unroll
    for (int s = 0; s < 8; s++) {
        // convert current A chunk to fp16 fragments
        uint32_t ah[8];
        #pragma unroll
        for (int j = 0; j < 4; j++) {
            ah[2 * j]     = f16x2(cur[j].x, cur[j].y);
            ah[2 * j + 1] = f16x2(cur[j].z, cur[j].w);
        }

        // prefetch next A chunk
        if (s < 7) {
            #pragma unroll
            for (int j = 0; j < 4; j++)
                cur[j] = *reinterpret_cast<const float4*>(
                    abase + (s + 1) * 16 + j * 8 * 128);
        }

        #pragma unroll
        for (int ntp = 0; ntp < 4; ntp++) {
            const uint32_t off = (uint32_t)(ntp * 16 * WPAD * 2 + s * 32);
            uint32_t bh[4], bl[4];
            ldsm4(bh, whi_base + off);
            ldsm4(bl, wlo_base + off);

            float* c00 = acc[0][2 * ntp];
            float* c01 = acc[0][2 * ntp + 1];
            float* c10 = acc[1][2 * ntp];
            float* c11 = acc[1][2 * ntp + 1];

            // term 1: A16 * Whi   (term-major: same-acc RAW distance 4)
            mma16816h(c00, ah[0], ah[2], ah[1], ah[3], bh[0], bh[1]);
            mma16816h(c01, ah[0], ah[2], ah[1], ah[3], bh[2], bh[3]);
            mma16816h(c10, ah[4], ah[6], ah[5], ah[7], bh[0], bh[1]);
            mma16816h(c11, ah[4], ah[6], ah[5], ah[7], bh[2], bh[3]);
            // term 2: A16 * Wlo
            mma16816h(c00, ah[0], ah[2], ah[1], ah[3], bl[0], bl[1]);
            mma16816h(c01, ah[0], ah[2], ah[1], ah[3], bl[2], bl[3]);
            mma16816h(c10, ah[4], ah[6], ah[5], ah[7], bl[0], bl[1]);
            mma16816h(c11, ah[4], ah[6], ah[5], ah[7], bl[2], bl[3]);
        }
    }

    // ---- epilogue: stage per-warp in smem (reuses W region), coalesced STG ----
    __syncthreads();   // all warps done reading W smem

    float* stage = reinterpret_cast<float*>(smem_raw) + warp * (16 * STG_STRIDE);
    const float4 bv4 = reinterpret_cast<const float4*>(bias)[lane & 15];
    const int r0 = lane >> 2;        // 0..7
    const int c0 = 2 * (lane & 3);   // 0,2,4,6
    const int rr = lane >> 4;        // 0/1
    const int cc = lane & 15;        // float4 col index

    #pragma unroll
    for (int f = 0; f < 2; f++) {
        __syncwarp();
        #pragma unroll
        for (int nt = 0; nt < 8; nt++) {
            *reinterpret_cast<float2*>(&stage[STG_STRIDE * r0 + 8 * nt + c0]) =
                make_float2(acc[f][nt][0], acc[f][nt][1]);
            *reinterpret_cast<float2*>(&stage[STG_STRIDE * (r0 + 8) + 8 * nt + c0]) =
                make_float2(acc[f][nt][2], acc[f][nt][3]);
        }
        __syncwarp();

        const long long rowbase = m0 + warp * 32 + f * 16;
        #pragma unroll
        for (int i = 0; i < 8; i++) {
            int r = 2 * i + rr;
            float4 v = *reinterpret_cast<float4*>(&stage[STG_STRIDE * r + 4 * cc]);
            v.x += bv4.x; v.y += bv4.y; v.z += bv4.z; v.w += bv4.w;
            *reinterpret_cast<float4*>(out + (rowbase + r) * 64 + 4 * cc) = v;
        }
    }
}

extern "C" void kernel_launch(void* const* d_in, const int* in_sizes, int n_in,
                              void* d_out, int out_size) {
    const float* ecg = (const float*)d_in[0];
    const float* W   = (const float*)d_in[1];
    const float* b   = (const float*)d_in[2];
    float* out = (float*)d_out;

    const int M = in_sizes[0] / 128;
    const long long xelems = (long long)M * 64;
    const int fillCount = out_size - (int)xelems;

    ecg_tok_mma<<<M / BM, THREADS>>>(ecg, W, b, out, xelems, fillCount);
}